// round 3
// baseline (speedup 1.0000x reference)
#include <cuda_runtime.h>
#include <cuda_bf16.h>

#define DIM    128
#define BATCH  8192
#define NITEMS 16384
#define RELS   500

typedef unsigned long long ull;

__device__ int   g_is64;
__device__ int   g_h[NITEMS];
__device__ int   g_r[NITEMS];
__device__ int   g_t[NITEMS];
__device__ float g_s[NITEMS];

__device__ __forceinline__ ull pack2(float a, float b) {
    ull r; asm("mov.b64 %0,{%1,%2};" : "=l"(r) : "f"(a), "f"(b)); return r;
}
__device__ __forceinline__ void ffma2(ull& d, ull a, ull b) {
    asm("fma.rn.f32x2 %0,%1,%2,%0;" : "+l"(d) : "l"(a), "l"(b));
}
__device__ __forceinline__ void unpack2(ull v, float& a, float& b) {
    asm("mov.b64 {%0,%1},%2;" : "=f"(a), "=f"(b) : "l"(v));
}

// int64 triples have all-zero high words (indices < 500)
__global__ void detect_dtype_kernel(const int* __restrict__ p) {
    if (threadIdx.x == 0) {
        int is64 = 1;
        #pragma unroll
        for (int i = 0; i < 16; i++)
            if (p[2 * i + 1] != 0) is64 = 0;
        g_is64 = is64;
    }
}

// Extract h/r/t as compact int32 columns (items 0..8191 = pos, 8192.. = neg)
__global__ void prep_kernel(const int* __restrict__ pos, const int* __restrict__ neg) {
    int i = blockIdx.x * blockDim.x + threadIdx.x;
    if (i >= NITEMS) return;
    const int sh = g_is64;             // int64: low word at index 2*k
    const int* q = (i < BATCH) ? pos : neg;
    const int  j = (i < BATCH) ? i : i - BATCH;
    g_h[i] = q[(3 * j + 0) << sh];
    g_r[i] = q[(3 * j + 1) << sh];
    g_t[i] = q[(3 * j + 2) << sh];
}

__global__ void __launch_bounds__(128) score_kernel(
    const float* __restrict__ ent,
    const float* __restrict__ rel,
    const float* __restrict__ tm)
{
    const int r    = blockIdx.x;       // relation id
    const int t    = threadIdx.x;
    const int lane = t & 31;
    const int w    = t >> 5;

    __shared__ __align__(16) float Mtile[16][DIM];   // staged Mr rows (LDS.128!)
    __shared__ __align__(16) float vbuf[64][DIM];    // 32 items x (h,t)
    __shared__ unsigned short list[1024];
    __shared__ int   s_cnt;
    __shared__ float rnorm[DIM];
    __shared__ float sbuf[4];
    __shared__ int   s_h[32], s_t[32];

    if (t == 0) s_cnt = 0;
    __syncthreads();

    // Build bucket: items whose relation == r
    for (int i = t; i < NITEMS; i += 128) {
        if (g_r[i] == r) {
            int p = atomicAdd(&s_cnt, 1);
            if (p < 1024) list[p] = (unsigned short)i;
        }
    }
    __syncthreads();
    const int n = min(s_cnt, 1024);
    if (n == 0) return;

    // Normalized relation vector (once per CTA)
    {
        float rv = rel[r * DIM + t];
        float v = rv * rv;
        #pragma unroll
        for (int o = 16; o > 0; o >>= 1) v += __shfl_xor_sync(0xffffffffu, v, o);
        if (lane == 0) sbuf[w] = v;
        __syncthreads();
        float ss = sbuf[0] + sbuf[1] + sbuf[2] + sbuf[3];
        rnorm[t] = rv / fmaxf(sqrtf(ss), 1e-12f);
    }

    const float* Mr = tm + (long long)r * (DIM * DIM);

    for (int base = 0; base < n; base += 32) {
        const int m = min(32, n - base);

        // Gather head/tail entity ids for this chunk
        if (t < 32 && t < m) {
            int id = list[base + t];
            s_h[t] = g_h[id];
            s_t[t] = g_t[id];
        }
        __syncthreads();

        // Load h/t vectors (zero-pad beyond m)
        for (int j = 0; j < 32; j++) {
            float hv = 0.f, tv = 0.f;
            if (j < m) {
                hv = ent[(long long)s_h[j] * DIM + t];
                tv = ent[(long long)s_t[j] * DIM + t];
            }
            vbuf[2 * j][t]     = hv;
            vbuf[2 * j + 1][t] = tv;
        }
        __syncthreads();

        // warp w owns vectors [16w, 16w+16); lane owns cols 4*lane..4*lane+3
        ull acc0[16], acc1[16];
        #pragma unroll
        for (int i = 0; i < 16; i++) { acc0[i] = 0ull; acc1[i] = 0ull; }

        const float* vb = &vbuf[16 * w][0];

        for (int d0 = 0; d0 < DIM; d0 += 16) {
            // Stage 16 Mr rows into smem (read from L2 once per CTA per chunk-pass)
            #pragma unroll
            for (int k = 0; k < 16; k++)
                Mtile[k][t] = Mr[(d0 + k) * DIM + t];
            __syncthreads();

            #pragma unroll 4
            for (int k = 0; k < 16; k++) {
                const float4 mm = *(const float4*)&Mtile[k][4 * lane];
                const ull m01 = pack2(mm.x, mm.y);
                const ull m23 = pack2(mm.z, mm.w);
                #pragma unroll
                for (int i = 0; i < 16; i++) {
                    float v = vb[i * DIM + d0 + k];   // smem broadcast
                    ull vv = pack2(v, v);
                    ffma2(acc0[i], m01, vv);
                    ffma2(acc1[i], m23, vv);
                }
            }
            __syncthreads();
        }

        // Epilogue: warp w handles chunk items j = 8w..8w+7
        #pragma unroll
        for (int jj = 0; jj < 8; jj++) {
            const int j = 8 * w + jj;
            float h0, h1, h2, h3, t0, t1, t2, t3;
            unpack2(acc0[2 * jj],     h0, h1);
            unpack2(acc1[2 * jj],     h2, h3);
            unpack2(acc0[2 * jj + 1], t0, t1);
            unpack2(acc1[2 * jj + 1], t2, t3);

            float nh = h0 * h0 + h1 * h1 + h2 * h2 + h3 * h3;
            float nt = t0 * t0 + t1 * t1 + t2 * t2 + t3 * t3;
            #pragma unroll
            for (int o = 16; o > 0; o >>= 1) {
                nh += __shfl_xor_sync(0xffffffffu, nh, o);
                nt += __shfl_xor_sync(0xffffffffu, nt, o);
            }
            const float ih = 1.0f / fmaxf(sqrtf(nh), 1e-12f);
            const float it = 1.0f / fmaxf(sqrtf(nt), 1e-12f);

            float s = fabsf(h0 * ih + rnorm[4 * lane + 0] - t0 * it)
                    + fabsf(h1 * ih + rnorm[4 * lane + 1] - t1 * it)
                    + fabsf(h2 * ih + rnorm[4 * lane + 2] - t2 * it)
                    + fabsf(h3 * ih + rnorm[4 * lane + 3] - t3 * it);
            #pragma unroll
            for (int o = 16; o > 0; o >>= 1)
                s += __shfl_xor_sync(0xffffffffu, s, o);

            if (lane == 0 && j < m)
                g_s[list[base + j]] = s;
        }
    }
}

__global__ void reduce_kernel(float* __restrict__ out) {
    __shared__ float sbuf[8];
    float v = 0.f;
    for (int i = threadIdx.x; i < BATCH; i += 256)
        v += fmaxf(g_s[i] - g_s[i + BATCH] + 1.0f, 0.0f);
    #pragma unroll
    for (int o = 16; o > 0; o >>= 1)
        v += __shfl_xor_sync(0xffffffffu, v, o);
    int w = threadIdx.x >> 5;
    if ((threadIdx.x & 31) == 0) sbuf[w] = v;
    __syncthreads();
    if (threadIdx.x == 0) {
        float s = 0.f;
        #pragma unroll
        for (int i = 0; i < 8; i++) s += sbuf[i];
        out[0] = s * (1.0f / (float)BATCH);
    }
}

extern "C" void kernel_launch(void* const* d_in, const int* in_sizes, int n_in,
                              void* d_out, int out_size) {
    const void*  pos = d_in[0];
    const void*  neg = d_in[1];
    const float* ent = (const float*)d_in[2];
    const float* rel = (const float*)d_in[3];
    const float* tm  = (const float*)d_in[4];

    detect_dtype_kernel<<<1, 32>>>((const int*)pos);
    prep_kernel<<<(NITEMS + 255) / 256, 256>>>((const int*)pos, (const int*)neg);
    score_kernel<<<RELS, 128>>>(ent, rel, tm);
    reduce_kernel<<<1, 256>>>((float*)d_out);
}

// round 4
// speedup vs baseline: 1.2929x; 1.2929x over previous
#include <cuda_runtime.h>

#define DIM    128
#define BATCH  8192
#define NITEMS 16384
#define RELS   500
#define KB     16

typedef unsigned long long ull;

__device__ int   g_is64;
__device__ int   g_h[NITEMS], g_r[NITEMS], g_t[NITEMS];
__device__ int   g_cnt[512];
__device__ int   g_off[RELS + 1];
__device__ int   g_cur[RELS];
__device__ int   g_bucket[NITEMS];
__device__ float g_s[NITEMS];

__device__ __forceinline__ ull pack2(float a, float b) {
    ull r; asm("mov.b64 %0,{%1,%2};" : "=l"(r) : "f"(a), "f"(b)); return r;
}
__device__ __forceinline__ void ffma2(ull& d, ull a, ull b) {
    asm("fma.rn.f32x2 %0,%1,%2,%0;" : "+l"(d) : "l"(a), "l"(b));
}
__device__ __forceinline__ void unpack2(ull v, float& a, float& b) {
    asm("mov.b64 {%0,%1},%2;" : "=f"(a), "=f"(b) : "l"(v));
}

// int64 triples have all-zero high words (indices < 500)
__global__ void detect_dtype_kernel(const int* __restrict__ p) {
    if (threadIdx.x == 0) {
        int is64 = 1;
        #pragma unroll
        for (int i = 0; i < 16; i++)
            if (p[2 * i + 1] != 0) is64 = 0;
        g_is64 = is64;
    }
}

__global__ void zero_kernel() {
    g_cnt[threadIdx.x] = 0;
}

// Extract h/r/t columns + histogram relations
__global__ void prep_kernel(const int* __restrict__ pos, const int* __restrict__ neg) {
    int i = blockIdx.x * blockDim.x + threadIdx.x;
    if (i >= NITEMS) return;
    const int sh = g_is64;
    const int* q = (i < BATCH) ? pos : neg;
    const int  j = (i < BATCH) ? i : i - BATCH;
    int hh = q[(3 * j + 0) << sh];
    int rr = q[(3 * j + 1) << sh];
    int tt = q[(3 * j + 2) << sh];
    g_h[i] = hh; g_r[i] = rr; g_t[i] = tt;
    atomicAdd(&g_cnt[rr], 1);
}

__global__ void scan_kernel() {
    __shared__ int sm[512];
    int tid = threadIdx.x;
    int x = (tid < RELS) ? g_cnt[tid] : 0;
    sm[tid] = x;
    __syncthreads();
    #pragma unroll
    for (int o = 1; o < 512; o <<= 1) {
        int v = (tid >= o) ? sm[tid - o] : 0;
        __syncthreads();
        sm[tid] += v;
        __syncthreads();
    }
    int inc = sm[tid];
    if (tid < RELS) { g_off[tid + 1] = inc; g_cur[tid] = inc - x; }
    if (tid == 0) g_off[0] = 0;
}

__global__ void scatter_kernel() {
    int i = blockIdx.x * blockDim.x + threadIdx.x;
    if (i >= NITEMS) return;
    int p = atomicAdd(&g_cur[g_r[i]], 1);
    g_bucket[p] = i;
}

__global__ void __launch_bounds__(128, 4) score_kernel(
    const float* __restrict__ ent,
    const float* __restrict__ rel,
    const float* __restrict__ tm)
{
    const int r   = blockIdx.x;
    const int tid = threadIdx.x;
    const int tx  = tid & 15;      // col group
    const int ty  = tid >> 4;      // vec group

    __shared__ __align__(16) float Mtile[KB][DIM];   // k-panel of Mr
    __shared__ __align__(16) float Vpanel[KB][68];   // k-panel of 64 vectors (transposed)
    __shared__ float part[64][17];
    __shared__ float rnorm[DIM];
    __shared__ float inv[64];
    __shared__ int   s_eid[64];

    // Normalized relation vector
    float rnA0, rnA1, rnA2, rnA3, rnB0, rnB1, rnB2, rnB3;
    {
        float v = rel[r * DIM + tid];
        float ss = v * v;
        #pragma unroll
        for (int o = 16; o > 0; o >>= 1) ss += __shfl_xor_sync(0xffffffffu, ss, o);
        if ((tid & 31) == 0) part[0][tid >> 5] = ss;
        __syncthreads();
        float tot = part[0][0] + part[0][1] + part[0][2] + part[0][3];
        rnorm[tid] = v / fmaxf(sqrtf(tot), 1e-12f);
        __syncthreads();
        float4 ra = *(const float4*)&rnorm[4 * tx];
        float4 rb = *(const float4*)&rnorm[64 + 4 * tx];
        rnA0 = ra.x; rnA1 = ra.y; rnA2 = ra.z; rnA3 = ra.w;
        rnB0 = rb.x; rnB1 = rb.y; rnB2 = rb.z; rnB3 = rb.w;
        __syncthreads();
    }

    const int beg = g_off[r];
    const int n   = g_off[r + 1] - beg;
    const int nv  = 2 * n;
    const float* Mr = tm + (long long)r * (DIM * DIM);

    for (int slab = 0; slab < nv; slab += 64) {
        // Gather entity ids for this slab's 64 vectors (h,t interleaved)
        if (tid < 64) {
            int vec = slab + tid;
            int e = 0;
            if (vec < nv) {
                int id = g_bucket[beg + (vec >> 1)];
                e = (vec & 1) ? g_t[id] : g_h[id];
            }
            s_eid[tid] = e;
        }
        __syncthreads();

        ull acc[8][4];
        #pragma unroll
        for (int i = 0; i < 8; i++)
            #pragma unroll
            for (int j = 0; j < 4; j++) acc[i][j] = 0ull;

        for (int kb = 0; kb < DIM; kb += KB) {
            // Stage M k-panel (coalesced float4)
            #pragma unroll
            for (int idx = tid; idx < KB * DIM / 4; idx += 128) {
                int row = idx >> 5, c4 = idx & 31;
                *(float4*)&Mtile[row][c4 * 4] =
                    *(const float4*)&Mr[(kb + row) * DIM + c4 * 4];
            }
            // Stage V k-panel, transposed: Vpanel[k][vec]
            #pragma unroll
            for (int idx = tid; idx < 64 * KB / 4; idx += 128) {
                int v = idx >> 2, q = idx & 3;
                float4 f = *(const float4*)&ent[(long long)s_eid[v] * DIM + kb + q * 4];
                Vpanel[q * 4 + 0][v] = f.x;
                Vpanel[q * 4 + 1][v] = f.y;
                Vpanel[q * 4 + 2][v] = f.z;
                Vpanel[q * 4 + 3][v] = f.w;
            }
            __syncthreads();

            #pragma unroll
            for (int k = 0; k < KB; k++) {
                const float4 ma = *(const float4*)&Mtile[k][4 * tx];
                const float4 mb = *(const float4*)&Mtile[k][64 + 4 * tx];
                const ull mp0 = pack2(ma.x, ma.y);
                const ull mp1 = pack2(ma.z, ma.w);
                const ull mp2 = pack2(mb.x, mb.y);
                const ull mp3 = pack2(mb.z, mb.w);
                const float4 va = *(const float4*)&Vpanel[k][8 * ty];
                const float4 vb = *(const float4*)&Vpanel[k][8 * ty + 4];
                const float vs[8] = {va.x, va.y, va.z, va.w, vb.x, vb.y, vb.z, vb.w};
                #pragma unroll
                for (int i = 0; i < 8; i++) {
                    ull vv = pack2(vs[i], vs[i]);
                    ffma2(acc[i][0], mp0, vv);
                    ffma2(acc[i][1], mp1, vv);
                    ffma2(acc[i][2], mp2, vv);
                    ffma2(acc[i][3], mp3, vv);
                }
            }
            __syncthreads();
        }

        // Phase 1: per-vector sum of squares
        #pragma unroll
        for (int i = 0; i < 8; i++) {
            float a, b, c, d, e, f, g, h;
            unpack2(acc[i][0], a, b);
            unpack2(acc[i][1], c, d);
            unpack2(acc[i][2], e, f);
            unpack2(acc[i][3], g, h);
            part[8 * ty + i][tx] =
                a * a + b * b + c * c + d * d + e * e + f * f + g * g + h * h;
        }
        __syncthreads();
        if (tid < 64) {
            float ss = 0.f;
            #pragma unroll
            for (int x = 0; x < 16; x++) ss += part[tid][x];
            inv[tid] = 1.0f / fmaxf(sqrtf(ss), 1e-12f);
        }
        __syncthreads();

        // Phase 2: L1 score partials (h = even vec, t = odd vec of each pair)
        #pragma unroll
        for (int p = 0; p < 4; p++) {
            float h0, h1, h2, h3, h4, h5, h6, h7;
            float t0, t1, t2, t3, t4, t5, t6, t7;
            unpack2(acc[2 * p][0], h0, h1);
            unpack2(acc[2 * p][1], h2, h3);
            unpack2(acc[2 * p][2], h4, h5);
            unpack2(acc[2 * p][3], h6, h7);
            unpack2(acc[2 * p + 1][0], t0, t1);
            unpack2(acc[2 * p + 1][1], t2, t3);
            unpack2(acc[2 * p + 1][2], t4, t5);
            unpack2(acc[2 * p + 1][3], t6, t7);
            const float ih = inv[8 * ty + 2 * p];
            const float it = inv[8 * ty + 2 * p + 1];
            float sc = fabsf(h0 * ih + rnA0 - t0 * it)
                     + fabsf(h1 * ih + rnA1 - t1 * it)
                     + fabsf(h2 * ih + rnA2 - t2 * it)
                     + fabsf(h3 * ih + rnA3 - t3 * it)
                     + fabsf(h4 * ih + rnB0 - t4 * it)
                     + fabsf(h5 * ih + rnB1 - t5 * it)
                     + fabsf(h6 * ih + rnB2 - t6 * it)
                     + fabsf(h7 * ih + rnB3 - t7 * it);
            part[4 * ty + p][tx] = sc;
        }
        __syncthreads();
        if (tid < 32) {
            int item_local = (slab >> 1) + tid;
            if (item_local < n) {
                float s = 0.f;
                #pragma unroll
                for (int x = 0; x < 16; x++) s += part[tid][x];
                g_s[g_bucket[beg + item_local]] = s;
            }
        }
        __syncthreads();
    }
}

__global__ void reduce_kernel(float* __restrict__ out) {
    __shared__ float sbuf[8];
    float v = 0.f;
    for (int i = threadIdx.x; i < BATCH; i += 256)
        v += fmaxf(g_s[i] - g_s[i + BATCH] + 1.0f, 0.0f);
    #pragma unroll
    for (int o = 16; o > 0; o >>= 1)
        v += __shfl_xor_sync(0xffffffffu, v, o);
    int w = threadIdx.x >> 5;
    if ((threadIdx.x & 31) == 0) sbuf[w] = v;
    __syncthreads();
    if (threadIdx.x == 0) {
        float s = 0.f;
        #pragma unroll
        for (int i = 0; i < 8; i++) s += sbuf[i];
        out[0] = s * (1.0f / (float)BATCH);
    }
}

extern "C" void kernel_launch(void* const* d_in, const int* in_sizes, int n_in,
                              void* d_out, int out_size) {
    const void*  pos = d_in[0];
    const void*  neg = d_in[1];
    const float* ent = (const float*)d_in[2];
    const float* rel = (const float*)d_in[3];
    const float* tm  = (const float*)d_in[4];

    detect_dtype_kernel<<<1, 32>>>((const int*)pos);
    zero_kernel<<<1, 512>>>();
    prep_kernel<<<(NITEMS + 255) / 256, 256>>>((const int*)pos, (const int*)neg);
    scan_kernel<<<1, 512>>>();
    scatter_kernel<<<(NITEMS + 255) / 256, 256>>>();
    score_kernel<<<RELS, 128>>>(ent, rel, tm);
    reduce_kernel<<<1, 256>>>((float*)d_out);
}

// round 5
// speedup vs baseline: 1.3931x; 1.0775x over previous
#include <cuda_runtime.h>

#define DIM    128
#define BATCH  8192
#define NITEMS 16384
#define RELS   500
#define KB     16

typedef unsigned long long ull;

__device__ int   g_h[NITEMS], g_r[NITEMS], g_t[NITEMS];
__device__ int   g_cnt[512];            // zero at load; re-zeroed by reduce_kernel
__device__ int   g_off[RELS + 1];
__device__ int   g_cur[RELS];
__device__ int   g_bucket[NITEMS];
__device__ __align__(16) float g_s[NITEMS];

__device__ __forceinline__ ull pack2(float a, float b) {
    ull r; asm("mov.b64 %0,{%1,%2};" : "=l"(r) : "f"(a), "f"(b)); return r;
}
__device__ __forceinline__ void ffma2(ull& d, ull a, ull b) {
    asm("fma.rn.f32x2 %0,%1,%2,%0;" : "+l"(d) : "l"(a), "l"(b));
}
__device__ __forceinline__ void unpack2(ull v, float& a, float& b) {
    asm("mov.b64 {%0,%1},%2;" : "=f"(a), "=f"(b) : "l"(v));
}
__device__ __forceinline__ void cp_async16(void* sdst, const void* gsrc) {
    unsigned s = (unsigned)__cvta_generic_to_shared(sdst);
    asm volatile("cp.async.ca.shared.global [%0], [%1], 16;" :: "r"(s), "l"(gsrc));
}
__device__ __forceinline__ void cp_commit() { asm volatile("cp.async.commit_group;"); }
__device__ __forceinline__ void cp_wait0()  { asm volatile("cp.async.wait_group 0;" ::: "memory"); }

// Extract h/r/t columns + relation histogram. Dtype detected inline:
// int64 triples (indices < 500) have all-zero odd 32-bit words.
__global__ void prep_kernel(const int* __restrict__ pos, const int* __restrict__ neg) {
    int i = blockIdx.x * blockDim.x + threadIdx.x;
    if (i >= NITEMS) return;
    const int sh = ((pos[1] | pos[3] | pos[5] | pos[7] |
                     pos[9] | pos[11] | pos[13] | pos[15]) == 0) ? 1 : 0;
    const int* q = (i < BATCH) ? pos : neg;
    const int  j = (i < BATCH) ? i : i - BATCH;
    int rr = q[(3 * j + 1) << sh];
    g_h[i] = q[(3 * j + 0) << sh];
    g_r[i] = rr;
    g_t[i] = q[(3 * j + 2) << sh];
    atomicAdd(&g_cnt[rr], 1);
}

__global__ void scan_kernel() {      // 512 threads, warp-shuffle scan
    __shared__ int ws[16];
    const int tid = threadIdx.x, lane = tid & 31, w = tid >> 5;
    const int x = (tid < RELS) ? g_cnt[tid] : 0;
    int v = x;
    #pragma unroll
    for (int o = 1; o < 32; o <<= 1) {
        int u = __shfl_up_sync(0xffffffffu, v, o);
        if (lane >= o) v += u;
    }
    if (lane == 31) ws[w] = v;
    __syncthreads();
    if (w == 0) {
        int s = (lane < 16) ? ws[lane] : 0;
        #pragma unroll
        for (int o = 1; o < 16; o <<= 1) {
            int u = __shfl_up_sync(0xffffffffu, s, o);
            if (lane >= o) s += u;
        }
        if (lane < 16) ws[lane] = s;
    }
    __syncthreads();
    const int inc = v + ((w > 0) ? ws[w - 1] : 0);
    if (tid < RELS) { g_off[tid + 1] = inc; g_cur[tid] = inc - x; }
    if (tid == 0)   g_off[0] = 0;
}

__global__ void scatter_kernel() {
    int i = blockIdx.x * blockDim.x + threadIdx.x;
    if (i >= NITEMS) return;
    int p = atomicAdd(&g_cur[g_r[i]], 1);
    g_bucket[p] = i;
}

__global__ void __launch_bounds__(128, 4) score_kernel(
    const float* __restrict__ ent,
    const float* __restrict__ rel,
    const float* __restrict__ tm)
{
    const int r   = blockIdx.x;
    const int tid = threadIdx.x;
    const int tx  = tid & 15;      // col group (8 cols: 4tx.. and 64+4tx..)
    const int ty  = tid >> 4;      // vec group (8 vectors)

    __shared__ __align__(16) float Mt[2][KB][DIM];   // double-buffered M k-panels
    __shared__ __align__(16) float Vp[2][KB][68];    // double-buffered V k-panels (transposed)
    __shared__ float part[64][17];
    __shared__ float rnorm[DIM];
    __shared__ float inv[64];
    __shared__ int   s_eid[64];

    // Normalized relation vector
    float rnA0, rnA1, rnA2, rnA3, rnB0, rnB1, rnB2, rnB3;
    {
        float v = rel[r * DIM + tid];
        float ss = v * v;
        #pragma unroll
        for (int o = 16; o > 0; o >>= 1) ss += __shfl_xor_sync(0xffffffffu, ss, o);
        if ((tid & 31) == 0) part[0][tid >> 5] = ss;
        __syncthreads();
        float tot = part[0][0] + part[0][1] + part[0][2] + part[0][3];
        rnorm[tid] = v / fmaxf(sqrtf(tot), 1e-12f);
        __syncthreads();
        float4 ra = *(const float4*)&rnorm[4 * tx];
        float4 rb = *(const float4*)&rnorm[64 + 4 * tx];
        rnA0 = ra.x; rnA1 = ra.y; rnA2 = ra.z; rnA3 = ra.w;
        rnB0 = rb.x; rnB1 = rb.y; rnB2 = rb.z; rnB3 = rb.w;
        __syncthreads();
    }

    const int beg = g_off[r];
    const int n   = g_off[r + 1] - beg;
    const int nv  = 2 * n;
    const float* Mr = tm + (long long)r * (DIM * DIM);

    for (int slab = 0; slab < nv; slab += 64) {
        // Gather entity ids for this slab's 64 vectors (h,t interleaved)
        if (tid < 64) {
            int vec = slab + tid;
            int e = 0;
            if (vec < nv) {
                int id = g_bucket[beg + (vec >> 1)];
                e = (vec & 1) ? g_t[id] : g_h[id];
            }
            s_eid[tid] = e;
        }
        __syncthreads();

        ull acc[8][4];
        #pragma unroll
        for (int i = 0; i < 8; i++)
            #pragma unroll
            for (int j = 0; j < 4; j++) acc[i][j] = 0ull;

        float4 vr[2];

        // ---- prologue: stage panel 0 into buffer 0 ----
        {
            #pragma unroll
            for (int j = 0; j < 4; j++) {
                int idx = tid + 128 * j, row = idx >> 5, c4 = idx & 31;
                cp_async16(&Mt[0][row][c4 * 4], &Mr[row * DIM + c4 * 4]);
            }
            cp_commit();
            #pragma unroll
            for (int j = 0; j < 2; j++) {
                int idx = tid + 128 * j, v = idx >> 2, q = idx & 3;
                vr[j] = *(const float4*)&ent[(long long)s_eid[v] * DIM + q * 4];
            }
            cp_wait0();
            #pragma unroll
            for (int j = 0; j < 2; j++) {
                int idx = tid + 128 * j, v = idx >> 2, q = idx & 3;
                Vp[0][q * 4 + 0][v] = vr[j].x;
                Vp[0][q * 4 + 1][v] = vr[j].y;
                Vp[0][q * 4 + 2][v] = vr[j].z;
                Vp[0][q * 4 + 3][v] = vr[j].w;
            }
            __syncthreads();
        }

        #pragma unroll 1
        for (int kbi = 0; kbi < 8; kbi++) {
            const int cur = kbi & 1, nxt = cur ^ 1;
            const int kb2 = (kbi + 1) * KB;

            // issue next panel's loads before computing current
            if (kbi < 7) {
                #pragma unroll
                for (int j = 0; j < 4; j++) {
                    int idx = tid + 128 * j, row = idx >> 5, c4 = idx & 31;
                    cp_async16(&Mt[nxt][row][c4 * 4], &Mr[(kb2 + row) * DIM + c4 * 4]);
                }
                cp_commit();
                #pragma unroll
                for (int j = 0; j < 2; j++) {
                    int idx = tid + 128 * j, v = idx >> 2, q = idx & 3;
                    vr[j] = *(const float4*)&ent[(long long)s_eid[v] * DIM + kb2 + q * 4];
                }
            }

            // ---- compute on current buffer ----
            #pragma unroll
            for (int k = 0; k < KB; k++) {
                const ull* mrow = (const ull*)&Mt[cur][k][0];
                const ull mp0 = mrow[2 * tx];
                const ull mp1 = mrow[2 * tx + 1];
                const ull mp2 = mrow[32 + 2 * tx];
                const ull mp3 = mrow[32 + 2 * tx + 1];
                const float4 va = *(const float4*)&Vp[cur][k][8 * ty];
                const float4 vb = *(const float4*)&Vp[cur][k][8 * ty + 4];
                const float vs[8] = {va.x, va.y, va.z, va.w, vb.x, vb.y, vb.z, vb.w};
                #pragma unroll
                for (int i = 0; i < 8; i++) {
                    ull vv = pack2(vs[i], vs[i]);
                    ffma2(acc[i][0], mp0, vv);
                    ffma2(acc[i][1], mp1, vv);
                    ffma2(acc[i][2], mp2, vv);
                    ffma2(acc[i][3], mp3, vv);
                }
            }

            if (kbi < 7) {
                cp_wait0();
                #pragma unroll
                for (int j = 0; j < 2; j++) {
                    int idx = tid + 128 * j, v = idx >> 2, q = idx & 3;
                    Vp[nxt][q * 4 + 0][v] = vr[j].x;
                    Vp[nxt][q * 4 + 1][v] = vr[j].y;
                    Vp[nxt][q * 4 + 2][v] = vr[j].z;
                    Vp[nxt][q * 4 + 3][v] = vr[j].w;
                }
            }
            __syncthreads();
        }

        // Phase 1: per-vector sum of squares
        #pragma unroll
        for (int i = 0; i < 8; i++) {
            float a, b, c, d, e, f, g, h;
            unpack2(acc[i][0], a, b);
            unpack2(acc[i][1], c, d);
            unpack2(acc[i][2], e, f);
            unpack2(acc[i][3], g, h);
            part[8 * ty + i][tx] =
                a * a + b * b + c * c + d * d + e * e + f * f + g * g + h * h;
        }
        __syncthreads();
        if (tid < 64) {
            float ss = 0.f;
            #pragma unroll
            for (int x = 0; x < 16; x++) ss += part[tid][x];
            inv[tid] = 1.0f / fmaxf(sqrtf(ss), 1e-12f);
        }
        __syncthreads();

        // Phase 2: L1 score partials (h = even vec, t = odd vec of each pair)
        #pragma unroll
        for (int p = 0; p < 4; p++) {
            float h0, h1, h2, h3, h4, h5, h6, h7;
            float t0, t1, t2, t3, t4, t5, t6, t7;
            unpack2(acc[2 * p][0], h0, h1);
            unpack2(acc[2 * p][1], h2, h3);
            unpack2(acc[2 * p][2], h4, h5);
            unpack2(acc[2 * p][3], h6, h7);
            unpack2(acc[2 * p + 1][0], t0, t1);
            unpack2(acc[2 * p + 1][1], t2, t3);
            unpack2(acc[2 * p + 1][2], t4, t5);
            unpack2(acc[2 * p + 1][3], t6, t7);
            const float ih = inv[8 * ty + 2 * p];
            const float it = inv[8 * ty + 2 * p + 1];
            float sc = fabsf(h0 * ih + rnA0 - t0 * it)
                     + fabsf(h1 * ih + rnA1 - t1 * it)
                     + fabsf(h2 * ih + rnA2 - t2 * it)
                     + fabsf(h3 * ih + rnA3 - t3 * it)
                     + fabsf(h4 * ih + rnB0 - t4 * it)
                     + fabsf(h5 * ih + rnB1 - t5 * it)
                     + fabsf(h6 * ih + rnB2 - t6 * it)
                     + fabsf(h7 * ih + rnB3 - t7 * it);
            part[4 * ty + p][tx] = sc;
        }
        __syncthreads();
        if (tid < 32) {
            int item_local = (slab >> 1) + tid;
            if (item_local < n) {
                float s = 0.f;
                #pragma unroll
                for (int x = 0; x < 16; x++) s += part[tid][x];
                g_s[g_bucket[beg + item_local]] = s;
            }
        }
        __syncthreads();
    }
}

__global__ void reduce_kernel(float* __restrict__ out) {   // 1024 threads
    __shared__ float sbuf[32];
    const int tid = threadIdx.x;
    float v = 0.f;
    #pragma unroll
    for (int it = 0; it < 2; it++) {
        int i = tid + 1024 * it;               // i in [0, 2048): float4 index
        float4 p = *(const float4*)&g_s[4 * i];
        float4 q = *(const float4*)&g_s[4 * i + BATCH];
        v += fmaxf(p.x - q.x + 1.0f, 0.0f);
        v += fmaxf(p.y - q.y + 1.0f, 0.0f);
        v += fmaxf(p.z - q.z + 1.0f, 0.0f);
        v += fmaxf(p.w - q.w + 1.0f, 0.0f);
    }
    #pragma unroll
    for (int o = 16; o > 0; o >>= 1)
        v += __shfl_xor_sync(0xffffffffu, v, o);
    if ((tid & 31) == 0) sbuf[tid >> 5] = v;
    // re-zero histogram for the next graph replay (invariant: zero on entry)
    if (tid < 512) g_cnt[tid] = 0;
    __syncthreads();
    if (tid == 0) {
        float s = 0.f;
        #pragma unroll
        for (int i = 0; i < 32; i++) s += sbuf[i];
        out[0] = s * (1.0f / (float)BATCH);
    }
}

extern "C" void kernel_launch(void* const* d_in, const int* in_sizes, int n_in,
                              void* d_out, int out_size) {
    const void*  pos = d_in[0];
    const void*  neg = d_in[1];
    const float* ent = (const float*)d_in[2];
    const float* rel = (const float*)d_in[3];
    const float* tm  = (const float*)d_in[4];

    prep_kernel<<<(NITEMS + 255) / 256, 256>>>((const int*)pos, (const int*)neg);
    scan_kernel<<<1, 512>>>();
    scatter_kernel<<<(NITEMS + 255) / 256, 256>>>();
    score_kernel<<<RELS, 128>>>(ent, rel, tm);
    reduce_kernel<<<1, 1024>>>((float*)d_out);
}

// round 6
// speedup vs baseline: 1.9452x; 1.3963x over previous
#include <cuda_runtime.h>

#define DIM    128
#define BATCH  8192
#define NITEMS 16384
#define RELS   500
#define KB     16
#define MAXSLABS 1024

typedef unsigned long long ull;

__device__ int   g_h[NITEMS], g_r[NITEMS], g_t[NITEMS];
__device__ int   g_cnt[512];            // zero at load; re-zeroed by reduce_kernel
__device__ int   g_off[RELS + 1];
__device__ int   g_cur[RELS];
__device__ int   g_bucket[NITEMS];
__device__ int   g_slab[MAXSLABS];      // packed (r << 7) | slab_index
__device__ int   g_nslabs;
__device__ __align__(16) float g_s[NITEMS];

__device__ __forceinline__ ull pack2(float a, float b) {
    ull r; asm("mov.b64 %0,{%1,%2};" : "=l"(r) : "f"(a), "f"(b)); return r;
}
__device__ __forceinline__ void ffma2(ull& d, ull a, ull b) {
    asm("fma.rn.f32x2 %0,%1,%2,%0;" : "+l"(d) : "l"(a), "l"(b));
}
__device__ __forceinline__ void unpack2(ull v, float& a, float& b) {
    asm("mov.b64 {%0,%1},%2;" : "=f"(a), "=f"(b) : "l"(v));
}
__device__ __forceinline__ void cp_async16(void* sdst, const void* gsrc) {
    unsigned s = (unsigned)__cvta_generic_to_shared(sdst);
    asm volatile("cp.async.ca.shared.global [%0], [%1], 16;" :: "r"(s), "l"(gsrc));
}
__device__ __forceinline__ void cp_commit() { asm volatile("cp.async.commit_group;"); }
__device__ __forceinline__ void cp_wait0()  { asm volatile("cp.async.wait_group 0;" ::: "memory"); }

// Extract h/r/t columns + relation histogram. Dtype detected inline:
// int64 triples (indices < 500) have all-zero odd 32-bit words.
__global__ void prep_kernel(const int* __restrict__ pos, const int* __restrict__ neg) {
    int i = blockIdx.x * blockDim.x + threadIdx.x;
    if (i >= NITEMS) return;
    const int sh = ((pos[1] | pos[3] | pos[5] | pos[7] |
                     pos[9] | pos[11] | pos[13] | pos[15]) == 0) ? 1 : 0;
    const int* q = (i < BATCH) ? pos : neg;
    const int  j = (i < BATCH) ? i : i - BATCH;
    int rr = q[(3 * j + 1) << sh];
    g_h[i] = q[(3 * j + 0) << sh];
    g_r[i] = rr;
    g_t[i] = q[(3 * j + 2) << sh];
    atomicAdd(&g_cnt[rr], 1);
}

// Prefix-scan counts -> offsets; also build the slab worklist.
__global__ void scan_kernel() {      // 512 threads
    __shared__ int ws[16], ws2[16];
    const int tid = threadIdx.x, lane = tid & 31, w = tid >> 5;
    const int x  = (tid < RELS) ? g_cnt[tid] : 0;         // items for relation tid
    const int y  = (2 * x + 63) >> 6;                      // slabs for relation tid

    int v = x, u = y;
    #pragma unroll
    for (int o = 1; o < 32; o <<= 1) {
        int a = __shfl_up_sync(0xffffffffu, v, o);
        int b = __shfl_up_sync(0xffffffffu, u, o);
        if (lane >= o) { v += a; u += b; }
    }
    if (lane == 31) { ws[w] = v; ws2[w] = u; }
    __syncthreads();
    if (w == 0) {
        int s  = (lane < 16) ? ws[lane]  : 0;
        int s2 = (lane < 16) ? ws2[lane] : 0;
        #pragma unroll
        for (int o = 1; o < 16; o <<= 1) {
            int a = __shfl_up_sync(0xffffffffu, s,  o);
            int b = __shfl_up_sync(0xffffffffu, s2, o);
            if (lane >= o) { s += a; s2 += b; }
        }
        if (lane < 16) { ws[lane] = s; ws2[lane] = s2; }
    }
    __syncthreads();
    const int inc  = v + ((w > 0) ? ws[w - 1]  : 0);   // inclusive item scan
    const int incs = u + ((w > 0) ? ws2[w - 1] : 0);   // inclusive slab scan
    if (tid < RELS) {
        g_off[tid + 1] = inc;
        g_cur[tid]     = inc - x;
        int sb = incs - y;
        for (int s = 0; s < y; s++)
            g_slab[sb + s] = (tid << 7) | s;
    }
    if (tid == 0)   g_off[0] = 0;
    if (tid == 511) g_nslabs = incs;     // total slabs (lane 31 of last warp holds full sum)
}

__global__ void scatter_kernel() {
    int i = blockIdx.x * blockDim.x + threadIdx.x;
    if (i >= NITEMS) return;
    int p = atomicAdd(&g_cur[g_r[i]], 1);
    g_bucket[p] = i;
}

__global__ void __launch_bounds__(128, 4) score_kernel(
    const float* __restrict__ ent,
    const float* __restrict__ rel,
    const float* __restrict__ tm)
{
    const int b = blockIdx.x;
    if (b >= g_nslabs) return;
    const int packed = g_slab[b];
    const int r    = packed >> 7;
    const int slab = (packed & 127) << 6;    // first vector index of this slab

    const int tid = threadIdx.x;
    const int tx  = tid & 15;      // col group (8 cols: 4tx.. and 64+4tx..)
    const int ty  = tid >> 4;      // vec group (8 vectors)

    __shared__ __align__(16) float Mt[2][KB][DIM];   // double-buffered M k-panels
    __shared__ __align__(16) float Vp[2][KB][68];    // double-buffered V k-panels (transposed)
    __shared__ float rnorm[DIM];
    __shared__ float sbuf[4];
    __shared__ int   s_eid[64];

    const int beg = g_off[r];
    const int n   = g_off[r + 1] - beg;
    const int nv  = 2 * n;
    const float* Mr = tm + (long long)r * (DIM * DIM);

    // Normalized relation vector
    float rnA0, rnA1, rnA2, rnA3, rnB0, rnB1, rnB2, rnB3;
    {
        float v = rel[r * DIM + tid];
        float ss = v * v;
        #pragma unroll
        for (int o = 16; o > 0; o >>= 1) ss += __shfl_xor_sync(0xffffffffu, ss, o);
        if ((tid & 31) == 0) sbuf[tid >> 5] = ss;
        __syncthreads();
        float tot = sbuf[0] + sbuf[1] + sbuf[2] + sbuf[3];
        rnorm[tid] = v / fmaxf(sqrtf(tot), 1e-12f);
    }

    // Gather entity ids for this slab's 64 vectors (h,t interleaved)
    if (tid < 64) {
        int vec = slab + tid;
        int e = 0;
        if (vec < nv) {
            int id = g_bucket[beg + (vec >> 1)];
            e = (vec & 1) ? g_t[id] : g_h[id];
        }
        s_eid[tid] = e;
    }
    __syncthreads();

    float4 ra = *(const float4*)&rnorm[4 * tx];
    float4 rb = *(const float4*)&rnorm[64 + 4 * tx];
    rnA0 = ra.x; rnA1 = ra.y; rnA2 = ra.z; rnA3 = ra.w;
    rnB0 = rb.x; rnB1 = rb.y; rnB2 = rb.z; rnB3 = rb.w;

    ull acc[8][4];
    #pragma unroll
    for (int i = 0; i < 8; i++)
        #pragma unroll
        for (int j = 0; j < 4; j++) acc[i][j] = 0ull;

    float4 vr[2];

    // ---- prologue: stage panel 0 into buffer 0 ----
    {
        #pragma unroll
        for (int j = 0; j < 4; j++) {
            int idx = tid + 128 * j, row = idx >> 5, c4 = idx & 31;
            cp_async16(&Mt[0][row][c4 * 4], &Mr[row * DIM + c4 * 4]);
        }
        cp_commit();
        #pragma unroll
        for (int j = 0; j < 2; j++) {
            int idx = tid + 128 * j, v = idx >> 2, q = idx & 3;
            vr[j] = *(const float4*)&ent[(long long)s_eid[v] * DIM + q * 4];
        }
        cp_wait0();
        #pragma unroll
        for (int j = 0; j < 2; j++) {
            int idx = tid + 128 * j, v = idx >> 2, q = idx & 3;
            Vp[0][q * 4 + 0][v] = vr[j].x;
            Vp[0][q * 4 + 1][v] = vr[j].y;
            Vp[0][q * 4 + 2][v] = vr[j].z;
            Vp[0][q * 4 + 3][v] = vr[j].w;
        }
        __syncthreads();
    }

    #pragma unroll 1
    for (int kbi = 0; kbi < 8; kbi++) {
        const int cur = kbi & 1, nxt = cur ^ 1;
        const int kb2 = (kbi + 1) * KB;

        // issue next panel's loads before computing current
        if (kbi < 7) {
            #pragma unroll
            for (int j = 0; j < 4; j++) {
                int idx = tid + 128 * j, row = idx >> 5, c4 = idx & 31;
                cp_async16(&Mt[nxt][row][c4 * 4], &Mr[(kb2 + row) * DIM + c4 * 4]);
            }
            cp_commit();
            #pragma unroll
            for (int j = 0; j < 2; j++) {
                int idx = tid + 128 * j, v = idx >> 2, q = idx & 3;
                vr[j] = *(const float4*)&ent[(long long)s_eid[v] * DIM + kb2 + q * 4];
            }
        }

        // ---- compute on current buffer ----
        #pragma unroll
        for (int k = 0; k < KB; k++) {
            const ull* mrow = (const ull*)&Mt[cur][k][0];
            const ull mp0 = mrow[2 * tx];
            const ull mp1 = mrow[2 * tx + 1];
            const ull mp2 = mrow[32 + 2 * tx];
            const ull mp3 = mrow[32 + 2 * tx + 1];
            const float4 va = *(const float4*)&Vp[cur][k][8 * ty];
            const float4 vb = *(const float4*)&Vp[cur][k][8 * ty + 4];
            const float vs[8] = {va.x, va.y, va.z, va.w, vb.x, vb.y, vb.z, vb.w};
            #pragma unroll
            for (int i = 0; i < 8; i++) {
                ull vv = pack2(vs[i], vs[i]);
                ffma2(acc[i][0], mp0, vv);
                ffma2(acc[i][1], mp1, vv);
                ffma2(acc[i][2], mp2, vv);
                ffma2(acc[i][3], mp3, vv);
            }
        }

        if (kbi < 7) {
            cp_wait0();
            #pragma unroll
            for (int j = 0; j < 2; j++) {
                int idx = tid + 128 * j, v = idx >> 2, q = idx & 3;
                Vp[nxt][q * 4 + 0][v] = vr[j].x;
                Vp[nxt][q * 4 + 1][v] = vr[j].y;
                Vp[nxt][q * 4 + 2][v] = vr[j].z;
                Vp[nxt][q * 4 + 3][v] = vr[j].w;
            }
        }
        __syncthreads();
    }

    // ---- barrier-free epilogue: 16-lane (half-warp) shuffle reductions ----
    // Threads with equal ty are lanes {16*(ty&1) .. +16} of warp (ty>>1).
    float invv[8];
    #pragma unroll
    for (int i = 0; i < 8; i++) {
        float a, b, c, d, e, f, g, h;
        unpack2(acc[i][0], a, b);
        unpack2(acc[i][1], c, d);
        unpack2(acc[i][2], e, f);
        unpack2(acc[i][3], g, h);
        float ss = a * a + b * b + c * c + d * d + e * e + f * f + g * g + h * h;
        #pragma unroll
        for (int o = 1; o < 16; o <<= 1)
            ss += __shfl_xor_sync(0xffffffffu, ss, o);
        invv[i] = 1.0f / fmaxf(sqrtf(ss), 1e-12f);
    }

    #pragma unroll
    for (int p = 0; p < 4; p++) {
        float h0, h1, h2, h3, h4, h5, h6, h7;
        float t0, t1, t2, t3, t4, t5, t6, t7;
        unpack2(acc[2 * p][0], h0, h1);
        unpack2(acc[2 * p][1], h2, h3);
        unpack2(acc[2 * p][2], h4, h5);
        unpack2(acc[2 * p][3], h6, h7);
        unpack2(acc[2 * p + 1][0], t0, t1);
        unpack2(acc[2 * p + 1][1], t2, t3);
        unpack2(acc[2 * p + 1][2], t4, t5);
        unpack2(acc[2 * p + 1][3], t6, t7);
        const float ih = invv[2 * p];
        const float it = invv[2 * p + 1];
        float sc = fabsf(h0 * ih + rnA0 - t0 * it)
                 + fabsf(h1 * ih + rnA1 - t1 * it)
                 + fabsf(h2 * ih + rnA2 - t2 * it)
                 + fabsf(h3 * ih + rnA3 - t3 * it)
                 + fabsf(h4 * ih + rnB0 - t4 * it)
                 + fabsf(h5 * ih + rnB1 - t5 * it)
                 + fabsf(h6 * ih + rnB2 - t6 * it)
                 + fabsf(h7 * ih + rnB3 - t7 * it);
        #pragma unroll
        for (int o = 1; o < 16; o <<= 1)
            sc += __shfl_xor_sync(0xffffffffu, sc, o);
        if (tx == 0) {
            int item_local = (slab >> 1) + 4 * ty + p;
            if (item_local < n)
                g_s[g_bucket[beg + item_local]] = sc;
        }
    }
}

__global__ void reduce_kernel(float* __restrict__ out) {   // 1024 threads
    __shared__ float sbuf[32];
    const int tid = threadIdx.x;
    float v = 0.f;
    #pragma unroll
    for (int it = 0; it < 2; it++) {
        int i = tid + 1024 * it;               // i in [0, 2048): float4 index
        float4 p = *(const float4*)&g_s[4 * i];
        float4 q = *(const float4*)&g_s[4 * i + BATCH];
        v += fmaxf(p.x - q.x + 1.0f, 0.0f);
        v += fmaxf(p.y - q.y + 1.0f, 0.0f);
        v += fmaxf(p.z - q.z + 1.0f, 0.0f);
        v += fmaxf(p.w - q.w + 1.0f, 0.0f);
    }
    #pragma unroll
    for (int o = 16; o > 0; o >>= 1)
        v += __shfl_xor_sync(0xffffffffu, v, o);
    if ((tid & 31) == 0) sbuf[tid >> 5] = v;
    // re-zero histogram for the next graph replay (invariant: zero on entry)
    if (tid < 512) g_cnt[tid] = 0;
    __syncthreads();
    if (tid == 0) {
        float s = 0.f;
        #pragma unroll
        for (int i = 0; i < 32; i++) s += sbuf[i];
        out[0] = s * (1.0f / (float)BATCH);
    }
}

extern "C" void kernel_launch(void* const* d_in, const int* in_sizes, int n_in,
                              void* d_out, int out_size) {
    const void*  pos = d_in[0];
    const void*  neg = d_in[1];
    const float* ent = (const float*)d_in[2];
    const float* rel = (const float*)d_in[3];
    const float* tm  = (const float*)d_in[4];

    prep_kernel<<<(NITEMS + 255) / 256, 256>>>((const int*)pos, (const int*)neg);
    scan_kernel<<<1, 512>>>();
    scatter_kernel<<<(NITEMS + 255) / 256, 256>>>();
    score_kernel<<<MAXSLABS, 128>>>(ent, rel, tm);
    reduce_kernel<<<1, 1024>>>((float*)d_out);
}